// round 11
// baseline (speedup 1.0000x reference)
#include <cuda_runtime.h>
#include <cuda_fp16.h>
#include <math.h>

#define N_NODES   100000
#define N_EDGES   1600000
#define N_GRAPHS  1024
#define HDIM      64
#define EPSV      1e-7f
#define LOG2E     1.4426950408889634f
#define SHL2      57.707801635558536f   /* 40 * log2(e) */
#define PRE_BLKS  592
#define CHUNK     169                   /* ceil(N_NODES / PRE_BLKS) */

typedef unsigned long long ull;

// ---------------- scratch (static device globals; no allocation) -------------
// Invariants at kernel_launch entry (zero at load; restored by head_kernel):
//   g_deg[*] == 0.   g_barcnt is monotonic (never reset; barrier is
//   position-independent), so replays are deterministic.
__device__ float g_h0[N_NODES * HDIM];
__device__ float g_h1[N_NODES * HDIM];
__device__ float g_agg[N_NODES * HDIM];
__device__ float g_pool[N_GRAPHS * HDIM];
__device__ float g_cnt[N_GRAPHS];
__device__ int   g_deg[N_NODES];
__device__ int   g_off[N_NODES];
__device__ int   g_cursor[N_NODES];
__device__ int   g_bsum2[PRE_BLKS];
__device__ ull   g_barcnt;
__device__ int   g_src_s[N_EDGES];
__device__ unsigned g_ea_p[(size_t)N_EDGES * 32];   // dst-sorted fp16 messages (205 MB)

__device__ __forceinline__ void red4(float* p, float a, float b, float c, float d) {
    asm volatile("red.global.add.v4.f32 [%0], {%1,%2,%3,%4};"
                 :: "l"(p), "f"(a), "f"(b), "f"(c), "f"(d) : "memory");
}
__device__ __forceinline__ ull pack2(float x, float y) {
    ull r; asm("mov.b64 %0, {%1, %2};" : "=l"(r) : "f"(x), "f"(y)); return r;
}
__device__ __forceinline__ void unpack2(float& x, float& y, ull v) {
    asm("mov.b64 {%0, %1}, %2;" : "=f"(x), "=f"(y) : "l"(v));
}
__device__ __forceinline__ void fma2(ull& d, ull a, ull b) {
    asm("fma.rn.f32x2 %0, %1, %2, %0;" : "+l"(d) : "l"(a), "l"(b));
}
__device__ __forceinline__ ull fma2_3(ull a, ull b, ull c) {
    ull d; asm("fma.rn.f32x2 %0, %1, %2, %3;" : "=l"(d) : "l"(a), "l"(b), "l"(c)); return d;
}
__device__ __forceinline__ ull add2(ull a, ull b) {
    ull d; asm("add.rn.f32x2 %0, %1, %2;" : "=l"(d) : "l"(a), "l"(b)); return d;
}
__device__ __forceinline__ ull splat(float v) { return pack2(v, v); }

// grid barrier: monotonic ticket counter, no reset (replay-safe).
// All PRE_BLKS blocks are co-resident (4 CTAs/SM, tiny smem/regs).
__device__ __forceinline__ void gridbar() {
    __syncthreads();
    if (threadIdx.x == 0) {
        __threadfence();
        ull old;
        asm volatile("atom.global.add.u64 %0, [%1], 1;" : "=l"(old) : "l"(&g_barcnt) : "memory");
        ull target = (old / (ull)PRE_BLKS) * (ull)PRE_BLKS + (ull)PRE_BLKS;
        ull v;
        do {
            asm volatile("ld.global.acquire.gpu.b64 %0, [%1];" : "=l"(v) : "l"(&g_barcnt));
        } while (v < target);
    }
    __syncthreads();
}

// ---- prelude (persistent): proj h0, degree hist, zeroing, CSR scan ------------
__global__ void __launch_bounds__(256) prelude(const float* __restrict__ x,
                                               const float* __restrict__ W,
                                               const float* __restrict__ b,
                                               const int* __restrict__ edst,
                                               const int* __restrict__ batch) {
    __shared__ float4 sW[256];
    __shared__ float4 sb[16];
    __shared__ int sVal[CHUNK];
    __shared__ int sWsum[8];
    __shared__ int sPfx;
    int tid = threadIdx.x, bid = blockIdx.x;
    int lane = tid & 31, w = tid >> 5;
    sW[tid] = ((const float4*)W)[tid];
    if (tid < 16) sb[tid] = ((const float4*)b)[tid];
    __syncthreads();

    // phase A: hist + proj + zero (grid-stride; every t in [0, N_EDGES) once)
    for (int t = bid * 256 + tid; t < N_EDGES; t += PRE_BLKS * 256) {
        atomicAdd(&g_deg[__ldg(edst + t)], 1);
        if (t < N_GRAPHS * HDIM) g_pool[t] = 0.0f;
        if (t < N_GRAPHS) g_cnt[t] = 0.0f;
        int n = t >> 4, g = t & 15;
        if (n < N_NODES) {
            const float4* xr = (const float4*)(x + n * 16);
            float4 x0 = xr[0], x1 = xr[1], x2 = xr[2], x3 = xr[3];
            float4 acc = sb[g];
#define ISTEP(av, kk) { float4 wv = sW[(kk)*16 + g]; \
    acc.x = fmaf(av, wv.x, acc.x); acc.y = fmaf(av, wv.y, acc.y); \
    acc.z = fmaf(av, wv.z, acc.z); acc.w = fmaf(av, wv.w, acc.w); }
            ISTEP(x0.x, 0)  ISTEP(x0.y, 1)  ISTEP(x0.z, 2)  ISTEP(x0.w, 3)
            ISTEP(x1.x, 4)  ISTEP(x1.y, 5)  ISTEP(x1.z, 6)  ISTEP(x1.w, 7)
            ISTEP(x2.x, 8)  ISTEP(x2.y, 9)  ISTEP(x2.z, 10) ISTEP(x2.w, 11)
            ISTEP(x3.x, 12) ISTEP(x3.y, 13) ISTEP(x3.z, 14) ISTEP(x3.w, 15)
#undef ISTEP
            ((float4*)(g_h0 + (size_t)n * HDIM))[g] = acc;
        }
    }
    gridbar();

    // phase B: local scan of this block's CHUNK of degrees
    int base = bid * CHUNK;
    int d = base + tid;
    int v = (tid < CHUNK && d < N_NODES) ? g_deg[d] : 0;
    int inc = v;
#pragma unroll
    for (int o = 1; o < 32; o <<= 1) {
        int t = __shfl_up_sync(0xffffffffu, inc, o);
        if (lane >= o) inc += t;
    }
    if (lane == 31) sWsum[w] = inc;
    __syncthreads();
    if (w == 0 && lane < 8) {
        int s = sWsum[lane];
#pragma unroll
        for (int o = 1; o < 8; o <<= 1) {
            int t = __shfl_up_sync(0x000000ffu, s, o);
            if (lane >= o) s += t;
        }
        sWsum[lane] = s;
    }
    __syncthreads();
    int bb = (w > 0) ? sWsum[w - 1] : 0;
    if (tid < CHUNK) sVal[tid] = bb + inc - v;   // local exclusive
    if (tid == 0) g_bsum2[bid] = sWsum[7];       // block total
    __threadfence();
    gridbar();

    // phase C: prefix over earlier blocks, write off/cursor, g_cnt
    if (w == 0) {
        int p = 0;
        for (int j = lane; j < bid; j += 32) p += g_bsum2[j];
#pragma unroll
        for (int o = 16; o; o >>= 1) p += __shfl_xor_sync(0xffffffffu, p, o);
        if (lane == 0) sPfx = p;
    }
    __syncthreads();
    int P = sPfx;
    if (tid < CHUNK && d < N_NODES) {
        int o = P + sVal[tid];
        g_off[d] = o;
        g_cursor[d] = o;
    }
    int bg = (tid < CHUNK && d < N_NODES) ? __ldg(batch + d) : -1;
    unsigned m = __match_any_sync(0xffffffffu, bg);
    if (bg >= 0 && (int)(__ffs(m) - 1) == lane)
        atomicAdd(&g_cnt[bg], (float)__popc(m));
}

// ----- project + scatter: ea_p[pos] = half2(edge_attr[e] @ eW + eb), dst-sorted
__global__ void __launch_bounds__(256) project_scatter(const float* __restrict__ edge_attr,
                                                       const int* __restrict__ esrc,
                                                       const int* __restrict__ edst,
                                                       const float* __restrict__ eW,
                                                       const float* __restrict__ eb) {
    int lane = threadIdx.x & 31;
    int w = threadIdx.x >> 5;
    int ebase = (blockIdx.x * 8 + w) * 8;     // grid = N_EDGES/64 = 25000 exact

    ull W0 = __ldg((const ull*)(eW + 0 * 64) + lane);
    ull W1 = __ldg((const ull*)(eW + 1 * 64) + lane);
    ull W2 = __ldg((const ull*)(eW + 2 * 64) + lane);
    ull W3 = __ldg((const ull*)(eW + 3 * 64) + lane);
    ull W4 = __ldg((const ull*)(eW + 4 * 64) + lane);
    ull W5 = __ldg((const ull*)(eW + 5 * 64) + lane);
    ull W6 = __ldg((const ull*)(eW + 6 * 64) + lane);
    ull W7 = __ldg((const ull*)(eW + 7 * 64) + lane);
    ull BB = __ldg((const ull*)eb + lane);

    int mysrc = 0, mypos = 0;
    if (lane < 8) {
        int e = ebase + lane;
        mysrc = __ldg(esrc + e);
        int d = __ldg(edst + e);
        mypos = atomicAdd(&g_cursor[d], 1);
    }

#pragma unroll
    for (int j = 0; j < 8; j++) {
        const float4* ap = (const float4*)(edge_attr + (size_t)(ebase + j) * 8);
        float4 a0 = __ldg(ap), a1 = __ldg(ap + 1);
        ull E = fma2_3(splat(a0.x), W0, BB);
        fma2(E, splat(a0.y), W1);
        fma2(E, splat(a0.z), W2);
        fma2(E, splat(a0.w), W3);
        fma2(E, splat(a1.x), W4);
        fma2(E, splat(a1.y), W5);
        fma2(E, splat(a1.z), W6);
        fma2(E, splat(a1.w), W7);
        float t0, t1; unpack2(t0, t1, E);
        __half2 hh = __floats2half2_rn(t0, t1);
        int pos = __shfl_sync(0xffffffffu, mypos, j);
        g_ea_p[(size_t)pos * 32 + lane] = *(unsigned*)&hh;
    }
    if (lane < 8) g_src_s[mypos] = mysrc;
}

// ---- per-dst aggregation: warp/dst, quarter-warp edge quads -------------------
// lane = (q = edge-in-quad, fl = 8-feature block). Per 4 edges:
// 1 LDG.32 (srcs) + 1 LDG.128 (fp16 msgs, coalesced 512B) + 2 LDG.128 (h row).
__global__ void __launch_bounds__(256) agg_pass(int cur) {
    int lane = threadIdx.x & 31;
    int q  = lane >> 3;     // 0..3
    int fl = lane & 7;      // features fl*8 .. fl*8+7
    int d = blockIdx.x * 8 + (threadIdx.x >> 5);   // grid 12500 exact
    const float* h = cur ? g_h1 : g_h0;
    const ull* eap = (const ull*)g_ea_p;           // edge i at ull offset i*16

    const ull L2E2 = splat(LOG2E);
    const ull C2   = splat(-SHL2);

    int start = g_off[d];
    int end = start + g_deg[d];
    ull DEN[4] = {0ull, 0ull, 0ull, 0ull};
    ull NUM[4] = {0ull, 0ull, 0ull, 0ull};

    // one edge, 8 features: EA = 8 fp16 (ulonglong2), H = 8 fp32 (2x ulonglong2)
#define QBODY(EAv, HA, HB) { \
    unsigned w0_ = (unsigned)(EAv).x, w1_ = (unsigned)((EAv).x >> 32); \
    unsigned w2_ = (unsigned)(EAv).y, w3_ = (unsigned)((EAv).y >> 32); \
    float2 e0 = __half22float2(*(__half2*)&w0_); \
    float2 e1 = __half22float2(*(__half2*)&w1_); \
    float2 e2 = __half22float2(*(__half2*)&w2_); \
    float2 e3 = __half22float2(*(__half2*)&w3_); \
    ull E0 = add2(pack2(e0.x, e0.y), (HA).x); \
    ull E1 = add2(pack2(e1.x, e1.y), (HA).y); \
    ull E2 = add2(pack2(e2.x, e2.y), (HB).x); \
    ull E3 = add2(pack2(e3.x, e3.y), (HB).y); \
    float t0,t1,t2,t3,t4,t5,t6,t7; \
    unpack2(t0,t1,E0); unpack2(t2,t3,E1); unpack2(t4,t5,E2); unpack2(t6,t7,E3); \
    float m0=fmaxf(t0,0.f)+EPSV, m1=fmaxf(t1,0.f)+EPSV, m2=fmaxf(t2,0.f)+EPSV, m3=fmaxf(t3,0.f)+EPSV; \
    float m4=fmaxf(t4,0.f)+EPSV, m5=fmaxf(t5,0.f)+EPSV, m6=fmaxf(t6,0.f)+EPSV, m7=fmaxf(t7,0.f)+EPSV; \
    ull M0=pack2(m0,m1), M1=pack2(m2,m3), M2=pack2(m4,m5), M3=pack2(m6,m7); \
    ull A0=fma2_3(M0,L2E2,C2), A1=fma2_3(M1,L2E2,C2), A2=fma2_3(M2,L2E2,C2), A3=fma2_3(M3,L2E2,C2); \
    float a0,a1,a2,a3,a4,a5,a6,a7; \
    unpack2(a0,a1,A0); unpack2(a2,a3,A1); unpack2(a4,a5,A2); unpack2(a6,a7,A3); \
    ull X0=pack2(exp2f(a0),exp2f(a1)), X1=pack2(exp2f(a2),exp2f(a3)); \
    ull X2=pack2(exp2f(a4),exp2f(a5)), X3=pack2(exp2f(a6),exp2f(a7)); \
    DEN[0]=add2(DEN[0],X0); DEN[1]=add2(DEN[1],X1); DEN[2]=add2(DEN[2],X2); DEN[3]=add2(DEN[3],X3); \
    fma2(NUM[0],M0,X0); fma2(NUM[1],M1,X1); fma2(NUM[2],M2,X2); fma2(NUM[3],M3,X3); }

    int i = start;
    for (; i + 4 <= end; i += 4) {
        int s = __ldg(g_src_s + i + q);
        ulonglong2 EA = __ldg((const ulonglong2*)(eap + (size_t)(i + q) * 16 + fl * 2));
        ulonglong2 HA = __ldg((const ulonglong2*)(h + (size_t)s * HDIM + fl * 8));
        ulonglong2 HB = __ldg((const ulonglong2*)(h + (size_t)s * HDIM + fl * 8 + 4));
        QBODY(EA, HA, HB)
    }
    int rem = end - i;
    if (q < rem) {
        int s = __ldg(g_src_s + i + q);
        ulonglong2 EA = __ldg((const ulonglong2*)(eap + (size_t)(i + q) * 16 + fl * 2));
        ulonglong2 HA = __ldg((const ulonglong2*)(h + (size_t)s * HDIM + fl * 8));
        ulonglong2 HB = __ldg((const ulonglong2*)(h + (size_t)s * HDIM + fl * 8 + 4));
        QBODY(EA, HA, HB)
    }
#undef QBODY

    // combine quads: xor 8 then xor 16
#pragma unroll
    for (int p = 0; p < 4; p++) {
        DEN[p] = add2(DEN[p], __shfl_xor_sync(0xffffffffu, DEN[p], 8));
        NUM[p] = add2(NUM[p], __shfl_xor_sync(0xffffffffu, NUM[p], 8));
        DEN[p] = add2(DEN[p], __shfl_xor_sync(0xffffffffu, DEN[p], 16));
        NUM[p] = add2(NUM[p], __shfl_xor_sync(0xffffffffu, NUM[p], 16));
    }

    if (q == 0) {   // lanes 0-7 write their 8 features
        float dv[8], nv[8];
        unpack2(dv[0], dv[1], DEN[0]); unpack2(dv[2], dv[3], DEN[1]);
        unpack2(dv[4], dv[5], DEN[2]); unpack2(dv[6], dv[7], DEN[3]);
        unpack2(nv[0], nv[1], NUM[0]); unpack2(nv[2], nv[3], NUM[1]);
        unpack2(nv[4], nv[5], NUM[2]); unpack2(nv[6], nv[7], NUM[3]);
        float* op = g_agg + (size_t)d * HDIM + fl * 8;
        *(float4*)op = make_float4(nv[0] / fmaxf(dv[0], 1e-16f), nv[1] / fmaxf(dv[1], 1e-16f),
                                   nv[2] / fmaxf(dv[2], 1e-16f), nv[3] / fmaxf(dv[3], 1e-16f));
        *(float4*)(op + 4) = make_float4(nv[4] / fmaxf(dv[4], 1e-16f), nv[5] / fmaxf(dv[5], 1e-16f),
                                         nv[6] / fmaxf(dv[6], 1e-16f), nv[7] / fmaxf(dv[7], 1e-16f));
    }
}

// ---------------- node MLP: smem-tiled GEMM, packed f32x2 (+pool on last) ------
#define SX_STRIDE 68
#define SH_STRIDE 68
#define SMEM_FLOATS (8704 + 4352 + 8192)   // 21248 floats = 84992 bytes

__global__ void __launch_bounds__(256, 2) node_mlp(int cur, int last,
                                                   const float* __restrict__ W1,
                                                   const float* __restrict__ b1,
                                                   const float* __restrict__ W2,
                                                   const float* __restrict__ b2,
                                                   const int* __restrict__ batch) {
    extern __shared__ float sm[];
    float* sH  = sm;                 // [128][68]
    float* sX  = sm + 8704;          // [64][68]
    float* sW1 = sm + 8704 + 4352;   // [64][128]
    float* sW2 = sm + 8704;          // [128][64] phase-2 overlay

    int tid = threadIdx.x;
    int base = blockIdx.x * 64;
    const float* h_in  = cur ? g_h1 : g_h0;
    float*       h_out = cur ? g_h0 : g_h1;

    {
        const float4* w4 = (const float4*)W1;
        float4* s4 = (float4*)sW1;
#pragma unroll
        for (int i = 0; i < 8; i++) s4[tid + i * 256] = w4[tid + i * 256];
    }
    for (int idx = tid; idx < 64 * 64; idx += 256) {
        int n = idx >> 6, f = idx & 63;
        int gn = base + n;
        float v = 0.0f;
        if (gn < N_NODES)
            v = h_in[(size_t)gn * HDIM + f] + g_agg[(size_t)gn * HDIM + f];
        sX[f * SX_STRIDE + n] = v;
    }
    __syncthreads();

    int nodeg = tid & 15;
    int hidg  = tid >> 4;

    ull acc[4][4];
    {
        float4 ba = *(const float4*)&b1[hidg * 8];
        float4 bbv = *(const float4*)&b1[hidg * 8 + 4];
        ull p0 = pack2(ba.x, ba.y), p1 = pack2(ba.z, ba.w);
        ull p2 = pack2(bbv.x, bbv.y), p3 = pack2(bbv.z, bbv.w);
#pragma unroll
        for (int n = 0; n < 4; n++) { acc[n][0] = p0; acc[n][1] = p1; acc[n][2] = p2; acc[n][3] = p3; }
    }
#pragma unroll 4
    for (int k = 0; k < 64; k++) {
        float4 xv = *(const float4*)&sX[k * SX_STRIDE + nodeg * 4];
        ulonglong2 wA = *(const ulonglong2*)&sW1[k * 128 + hidg * 8];
        ulonglong2 wB = *(const ulonglong2*)&sW1[k * 128 + hidg * 8 + 4];
        float xs[4] = { xv.x, xv.y, xv.z, xv.w };
#pragma unroll
        for (int n = 0; n < 4; n++) {
            ull xd = pack2(xs[n], xs[n]);
            fma2(acc[n][0], xd, wA.x);
            fma2(acc[n][1], xd, wA.y);
            fma2(acc[n][2], xd, wB.x);
            fma2(acc[n][3], xd, wB.y);
        }
    }
#pragma unroll
    for (int p = 0; p < 4; p++) {
        float lo[4], hi[4];
#pragma unroll
        for (int n = 0; n < 4; n++) unpack2(lo[n], hi[n], acc[n][p]);
        *(float4*)&sH[(hidg * 8 + 2 * p) * SH_STRIDE + nodeg * 4] =
            make_float4(fmaxf(lo[0], 0.f), fmaxf(lo[1], 0.f), fmaxf(lo[2], 0.f), fmaxf(lo[3], 0.f));
        *(float4*)&sH[(hidg * 8 + 2 * p + 1) * SH_STRIDE + nodeg * 4] =
            make_float4(fmaxf(hi[0], 0.f), fmaxf(hi[1], 0.f), fmaxf(hi[2], 0.f), fmaxf(hi[3], 0.f));
    }
    __syncthreads();

    {
        const float4* w4 = (const float4*)W2;
        float4* s4 = (float4*)sW2;
#pragma unroll
        for (int i = 0; i < 8; i++) s4[tid + i * 256] = w4[tid + i * 256];
    }
    __syncthreads();

    int outg = tid >> 4;
    ull a2[4][2];
    {
        float4 bv = *(const float4*)&b2[outg * 4];
        ull p0 = pack2(bv.x, bv.y), p1 = pack2(bv.z, bv.w);
#pragma unroll
        for (int n = 0; n < 4; n++) { a2[n][0] = p0; a2[n][1] = p1; }
    }
#pragma unroll 4
    for (int k = 0; k < 128; k++) {
        float4 hv = *(const float4*)&sH[k * SH_STRIDE + nodeg * 4];
        ulonglong2 wp = *(const ulonglong2*)&sW2[k * 64 + outg * 4];
        float hs[4] = { hv.x, hv.y, hv.z, hv.w };
#pragma unroll
        for (int n = 0; n < 4; n++) {
            ull xd = pack2(hs[n], hs[n]);
            fma2(a2[n][0], xd, wp.x);
            fma2(a2[n][1], xd, wp.y);
        }
    }
#pragma unroll
    for (int n = 0; n < 4; n++) {
        int gn = base + nodeg * 4 + n;
        if (gn < N_NODES) {
            float r0, r1, r2, r3;
            unpack2(r0, r1, a2[n][0]);
            unpack2(r2, r3, a2[n][1]);
            r0 = fmaxf(r0, 0.f); r1 = fmaxf(r1, 0.f);
            r2 = fmaxf(r2, 0.f); r3 = fmaxf(r3, 0.f);
            if (last) {
                int b = __ldg(batch + gn);
                red4(g_pool + (size_t)b * HDIM + outg * 4, r0, r1, r2, r3);
            } else {
                *(float4*)&h_out[(size_t)gn * HDIM + outg * 4] = make_float4(r0, r1, r2, r3);
            }
        }
    }
}

// --------- graph head (restores g_deg invariant for next call) -----------------
__global__ void __launch_bounds__(256) head_kernel(const float* __restrict__ graph_attr,
                                                   const float* __restrict__ d1W, const float* __restrict__ d1b,
                                                   const float* __restrict__ d2W, const float* __restrict__ d2b,
                                                   const float* __restrict__ oW,  const float* __restrict__ ob,
                                                   float* __restrict__ out) {
    int t = blockIdx.x * 256 + threadIdx.x;
    for (int i = t; i < N_NODES; i += (N_GRAPHS * 32)) g_deg[i] = 0;

    int g = t >> 5, lane = t & 31;
    if (g >= N_GRAPHS) return;
    float cnt = fmaxf(g_cnt[g], 1.0f);
    float p0 = g_pool[g * HDIM + lane] / cnt;
    float p1 = g_pool[g * HDIM + 32 + lane] / cnt;
    float ga = (lane < 10) ? graph_attr[g * 10 + lane] : 0.0f;

    float a = d1b[lane];
#pragma unroll
    for (int k = 0; k < 32; k++) a = fmaf(__shfl_sync(0xffffffffu, p0, k), d1W[k * 32 + lane], a);
#pragma unroll
    for (int k = 0; k < 32; k++) a = fmaf(__shfl_sync(0xffffffffu, p1, k), d1W[(32 + k) * 32 + lane], a);
#pragma unroll
    for (int k = 0; k < 10; k++) a = fmaf(__shfl_sync(0xffffffffu, ga, k), d1W[(64 + k) * 32 + lane], a);
    a = fmaxf(a, 0.0f);

    float bsum = d2b[lane];
#pragma unroll
    for (int k = 0; k < 32; k++) bsum = fmaf(__shfl_sync(0xffffffffu, a, k), d2W[k * 32 + lane], bsum);
    bsum = fmaxf(bsum, 0.0f);

    float v = bsum * oW[lane];
#pragma unroll
    for (int s = 16; s > 0; s >>= 1) v += __shfl_xor_sync(0xffffffffu, v, s);
    if (lane == 0) out[g] = 1.0f / (1.0f + expf(-(v + ob[0])));
}

// ---------------- launch -------------------------------------------------------
extern "C" void kernel_launch(void* const* d_in, const int* in_sizes, int n_in,
                              void* d_out, int out_size) {
    const float* x          = (const float*)d_in[0];
    const float* edge_attr  = (const float*)d_in[1];
    const float* graph_attr = (const float*)d_in[2];
    const int*   edge_index = (const int*)d_in[3];
    const int*   batch      = (const int*)d_in[4];
    const float* node_W     = (const float*)d_in[5];
    const float* node_b     = (const float*)d_in[6];
    const float* edge_W     = (const float*)d_in[7];
    const float* edge_b     = (const float*)d_in[8];
    const float* cW1[3] = { (const float*)d_in[9],  (const float*)d_in[13], (const float*)d_in[17] };
    const float* cb1[3] = { (const float*)d_in[10], (const float*)d_in[14], (const float*)d_in[18] };
    const float* cW2[3] = { (const float*)d_in[11], (const float*)d_in[15], (const float*)d_in[19] };
    const float* cb2[3] = { (const float*)d_in[12], (const float*)d_in[16], (const float*)d_in[20] };
    const float* d1W = (const float*)d_in[21];
    const float* d1b = (const float*)d_in[22];
    const float* d2W = (const float*)d_in[23];
    const float* d2b = (const float*)d_in[24];
    const float* oW  = (const float*)d_in[25];
    const float* ob  = (const float*)d_in[26];
    const int* esrc = edge_index;
    const int* edst = edge_index + N_EDGES;
    float* out = (float*)d_out;

    const int SMEM_MLP = SMEM_FLOATS * 4;   // 84992 bytes
    cudaFuncSetAttribute((const void*)node_mlp,
                         cudaFuncAttributeMaxDynamicSharedMemorySize, SMEM_MLP);

    // 1: persistent prelude (proj + hist + zero + grid-barrier scan)
    prelude<<<PRE_BLKS, 256>>>(x, node_W, node_b, edst, batch);
    // 2: project ea once (fp16) + scatter to dst order
    project_scatter<<<N_EDGES / 64, 256>>>(edge_attr, esrc, edst, edge_W, edge_b);

    int cur = 0;
    const int NBLK_MLP = (N_NODES + 63) / 64;
    for (int c = 0; c < 3; c++) {
        agg_pass<<<N_NODES / 8, 256>>>(cur);
        // c==0: launch #4 = node_mlp -> ncu capture slot (first profile of mlp)
        node_mlp<<<NBLK_MLP, 256, SMEM_MLP>>>(cur, (c == 2) ? 1 : 0,
                                              cW1[c], cb1[c], cW2[c], cb2[c], batch);
        cur ^= 1;
    }

    head_kernel<<<(N_GRAPHS * 32) / 256, 256>>>(graph_attr, d1W, d1b, d2W, d2b, oW, ob, out);
}